// round 17
// baseline (speedup 1.0000x reference)
#include <cuda_runtime.h>
#include <cuda_bf16.h>

// Wav2Frames: out[b, c, f] = x[b, f*WINSTEP + c]
// x: (32, 1, 480000) fp32 -> out: (32, 400, 2998) fp32
//
// R17 = R10 schedule/alignment (confirmed 3x) + quad-store drain:
//  - skew changed j+(j>>5) -> j+(j>>7): drain lane stride 640 floats gives
//    bank step 5 (gcd(5,32)=1) -> ALL drain LDS conflict-free (was 2-way);
//    fill float4 STS also conflict-free under this skew.
//  - lane owns a frame QUAD: 4x scalar LDS + 1x STG.128 per 4 elements
//    (was 2x LDS + STG.64 per 2): STG count halved, smem phases halved.
//  - alignment: s(c)=(2c)&7 => s == 2c (mod 4) => 16B-aligned STG.128.
//  - row chunk stays 448B (length preserved; R15 trap avoided).
//  - last tile: s in {0,4} leaves frames {2996,2997} -> float2 fixup.

#define B        32
#define T        480000
#define WINLEN   400
#define WINSTEP  160
#define NFRAMES  2998
#define F_TILE   112
#define NTILES   27                                    // 27*112 = 3024 >= 2998
#define NQUADS   (F_TILE / 4)                          // 28 frame quads
#define SPAN     ((F_TILE - 1) * WINSTEP + WINLEN + 6 * WINSTEP)  // 19120
#define SM_SZ    (SPAN + SPAN / 128 + 8)               // 19277 floats (~77.1 KB)
#define THREADS  1024

__device__ __forceinline__ int skew(int j) { return j + (j >> 7); }

__global__ __launch_bounds__(THREADS, 2)
void wav2frames_kernel(const float* __restrict__ x, float* __restrict__ out) {
    extern __shared__ float sm[];

    const int tile = blockIdx.x;
    const int b    = blockIdx.y;
    const int tid  = threadIdx.x;
    const int lane = tid & 31;
    const int w    = tid >> 5;                         // 32 warps

    const int f0 = tile * F_TILE;                      // multiple of 16
    const int x0 = f0 * WINSTEP;

    // ---- fill: float4 LDG (coalesced) -> skewed smem (conflict-free STS) ----
    const float* __restrict__ xb = x + (size_t)b * T + x0;
    const int span  = (x0 + SPAN <= T) ? SPAN : (T - x0);   // multiple of 4
    const int span4 = span >> 2;
    const float4* __restrict__ xb4 = reinterpret_cast<const float4*>(xb);

    for (int i4 = tid; i4 < span4; i4 += THREADS) {    // ~5 iterations
        const float4 v = xb4[i4];
        const int p = skew(i4 << 2);                   // 4i + (i4>>5)
        sm[p + 0] = v.x;
        sm[p + 1] = v.y;
        sm[p + 2] = v.z;
        sm[p + 3] = v.w;
    }
    __syncthreads();

    float* __restrict__ outb = out + (size_t)b * WINLEN * NFRAMES;

    // ---- main store: 28 frame quads (lanes) x 32 c-rows (warps) ----
    // lane qi owns frames f0 + 4qi + s(c) .. +3;  STG.128, 16B-aligned.
    const int qi    = lane;                            // 0..31 (28 active)
    const int fbase = f0 + 4 * qi;
    const int jbase = 4 * qi * WINSTEP;                // 640 * qi

    if (qi < NQUADS) {
        #pragma unroll 5
        for (int c = w; c < WINLEN; c += 32) {         // 12-13 iterations
            const int s = (2 * c) & 7;                 // 0,2,4,6
            const int f = fbase + s;
            if (f <= NFRAMES - 4) {
                const int j0 = jbase + s * WINSTEP + c;
                float4 v;
                v.x = sm[skew(j0)];
                v.y = sm[skew(j0 + WINSTEP)];
                v.z = sm[skew(j0 + 2 * WINSTEP)];
                v.w = sm[skew(j0 + 3 * WINSTEP)];
                *reinterpret_cast<float4*>(outb + (size_t)c * NFRAMES + f) = v;
            }
        }
    }

    // ---- tail fixup (last tile): s in {0,4} leaves frames {2996, 2997} ----
    if (tile == NTILES - 1) {
        for (int c = tid; c < WINLEN; c += THREADS) {
            const int s = (2 * c) & 7;
            if (s == 0 || s == 4) {
                const int j0 = (2996 - f0) * WINSTEP + c;   // 13440 + c
                float2 v;
                v.x = sm[skew(j0)];
                v.y = sm[skew(j0 + WINSTEP)];
                *reinterpret_cast<float2*>(outb + (size_t)c * NFRAMES + 2996) = v;
            }
        }
    }

    // ---- head: tile 0 writes frames [0, s(c)) for each row c ----
    if (tile == 0) {
        for (int idx = tid; idx < WINLEN * 3; idx += THREADS) {
            const int c = idx / 3;
            const int m = idx - 3 * c;                 // pair slot 0..2
            const int s = (2 * c) & 7;
            if (2 * m < s) {
                const int fh = 2 * m;
                const int j0 = fh * WINSTEP + c;
                float2 v;
                v.x = sm[skew(j0)];
                v.y = sm[skew(j0 + WINSTEP)];
                *reinterpret_cast<float2*>(outb + (size_t)c * NFRAMES + fh) = v;
            }
        }
    }
}

extern "C" void kernel_launch(void* const* d_in, const int* in_sizes, int n_in,
                              void* d_out, int out_size) {
    const float* x = (const float*)d_in[0];            // (32, 1, 480000) fp32
    // d_in[1] = W (identity, unused), d_in[2] = winstep (fixed 160, unused)
    float* out = (float*)d_out;                        // (32, 400, 2998) fp32

    static bool configured = false;
    if (!configured) {
        cudaFuncSetAttribute(wav2frames_kernel,
                             cudaFuncAttributeMaxDynamicSharedMemorySize,
                             SM_SZ * (int)sizeof(float));
        configured = true;
    }

    dim3 grid(NTILES, B);                              // 27 x 32 = 864 CTAs
    wav2frames_kernel<<<grid, THREADS, SM_SZ * sizeof(float)>>>(x, out);
}